// round 14
// baseline (speedup 1.0000x reference)
#include <cuda_runtime.h>
#include <cuda_bf16.h>
#include <math.h>
#include <float.h>
#include <stdint.h>
typedef unsigned long long ull;

#define SQ   2048
#define DM   2048
#define H    16
#define DN   128
#define DRR  64
#define DV   128
#define QRr  1536
#define KRr  512
#define HIi  32
#define DIi  128
#define TOPK 512
#define DQK  192
#define INV_SQRT_DQK 0.07216878364870322f
#define INV_SQRT_DI  0.08838834764831845f
#define INV_SQRT_HI  0.17677669529663687f

__device__ float g_qr   [SQ * QRr];
__device__ float g_q    [SQ * H * DQK];
__device__ float g_kvall[SQ * (KRr + DRR)];
__device__ float g_kv   [SQ * KRr];
__device__ float g_kpe  [SQ * DRR];
__device__ float g_qi   [SQ * HIi * DIi];
__device__ float g_ki   [SQ * DIi];
__device__ float g_wts  [SQ * HIi];
__device__ float g_iscore[(size_t)SQ * SQ];
__device__ int   g_tidx [SQ * TOPK];
__device__ int   g_tcnt [SQ];
__device__ float g_qabs [(size_t)SQ * H * 512];
__device__ float g_lat  [(size_t)H * SQ * 512];
__device__ float g_attn [SQ * H * DV];

__device__ __forceinline__ ull pk2(float x, float y)
{ ull r; asm("mov.b64 %0, {%1, %2};" : "=l"(r) : "f"(x), "f"(y)); return r; }
__device__ __forceinline__ void fma2(ull &c, ull a, ull b)
{ asm("fma.rn.f32x2 %0, %1, %2, %0;" : "+l"(c) : "l"(a), "l"(b)); }
__device__ __forceinline__ float2 upk2(ull v)
{ float2 f; asm("mov.b64 {%0, %1}, %2;" : "=f"(f.x), "=f"(f.y) : "l"(v)); return f; }
__device__ __forceinline__ ull add2(ull a, ull b)
{ ull r; asm("add.rn.f32x2 %0, %1, %2;" : "=l"(r) : "l"(a), "l"(b)); return r; }

// ---------- SGEMM fp32x2 (frozen numerics; EXACT R11 body) ----------
__global__ __launch_bounds__(256) void sgemm_nt(
    const float* __restrict__ A, const float* __restrict__ B, float* __restrict__ C,
    int M, int N, int K)
{
    __shared__ float As[16][128];
    __shared__ float Bs[16][128];
    const int bm = blockIdx.x * 128, bn = blockIdx.y * 128;
    const int tid = threadIdx.x;
    const int lr = tid >> 2, lc = (tid & 3) << 2;
    const int tm = (tid >> 4) << 3, tn = (tid & 15) << 3;
    ull acc2[8][4];
#pragma unroll
    for (int i = 0; i < 8; i++)
#pragma unroll
        for (int j = 0; j < 4; j++) acc2[i][j] = 0ULL;
    for (int k0 = 0; k0 < K; k0 += 16) {
#pragma unroll
        for (int i = 0; i < 2; i++) {
            int r = lr + i * 64;
            float4 va = make_float4(0.f,0.f,0.f,0.f), vb = make_float4(0.f,0.f,0.f,0.f);
            if (bm + r < M) va = *(const float4*)(A + (size_t)(bm + r) * K + k0 + lc);
            if (bn + r < N) vb = *(const float4*)(B + (size_t)(bn + r) * K + k0 + lc);
            As[lc+0][r]=va.x; As[lc+1][r]=va.y; As[lc+2][r]=va.z; As[lc+3][r]=va.w;
            Bs[lc+0][r]=vb.x; Bs[lc+1][r]=vb.y; Bs[lc+2][r]=vb.z; Bs[lc+3][r]=vb.w;
        }
        __syncthreads();
#pragma unroll
        for (int kk = 0; kk < 16; kk++) {
            float a[8], b[8];
#pragma unroll
            for (int i = 0; i < 8; i++) a[i] = As[kk][tm + i];
#pragma unroll
            for (int j = 0; j < 8; j++) b[j] = Bs[kk][tn + j];
            ull b2[4];
#pragma unroll
            for (int j = 0; j < 4; j++) b2[j] = pk2(b[2*j], b[2*j+1]);
#pragma unroll
            for (int i = 0; i < 8; i++) {
                ull a2 = pk2(a[i], a[i]);
#pragma unroll
                for (int j = 0; j < 4; j++) fma2(acc2[i][j], a2, b2[j]);
            }
        }
        __syncthreads();
    }
#pragma unroll
    for (int i = 0; i < 8; i++) {
        int m = bm + tm + i;
        if (m >= M) continue;
#pragma unroll
        for (int j = 0; j < 4; j++) {
            float2 f = upk2(acc2[i][j]);
            int n = bn + tn + 2*j;
            if (n < N)     C[(size_t)m*N + n]     = f.x;
            if (n+1 < N)   C[(size_t)m*N + n + 1] = f.y;
        }
    }
}

// ---------- bf16x6 tensor GEMM, gmem prefetch pipelined (only change vs R11) ----------
__device__ __forceinline__ void split_pack(float x, float y,
                                           unsigned &ph, unsigned &pm, unsigned &pl)
{
    __nv_bfloat16 hx = __float2bfloat16(x);
    float rx = x - __bfloat162float(hx);
    __nv_bfloat16 mx = __float2bfloat16(rx);
    __nv_bfloat16 lx = __float2bfloat16(rx - __bfloat162float(mx));
    __nv_bfloat16 hy = __float2bfloat16(y);
    float ry = y - __bfloat162float(hy);
    __nv_bfloat16 my = __float2bfloat16(ry);
    __nv_bfloat16 ly = __float2bfloat16(ry - __bfloat162float(my));
    ph = (unsigned)__bfloat16_as_ushort(hx) | ((unsigned)__bfloat16_as_ushort(hy) << 16);
    pm = (unsigned)__bfloat16_as_ushort(mx) | ((unsigned)__bfloat16_as_ushort(my) << 16);
    pl = (unsigned)__bfloat16_as_ushort(lx) | ((unsigned)__bfloat16_as_ushort(ly) << 16);
}

#define MMA_BF16(cc, aa, bb)                                                     \
    asm volatile(                                                                \
        "mma.sync.aligned.m16n8k16.row.col.f32.bf16.bf16.f32 "                   \
        "{%0,%1,%2,%3},{%4,%5,%6,%7},{%8,%9},{%0,%1,%2,%3};\n"                   \
        : "+f"((cc)[0]), "+f"((cc)[1]), "+f"((cc)[2]), "+f"((cc)[3])             \
        : "r"((aa)[0]), "r"((aa)[1]), "r"((aa)[2]), "r"((aa)[3]),                \
          "r"((bb)[0]), "r"((bb)[1]))

__global__ __launch_bounds__(256) void gemm_bf16x6(
    const float* __restrict__ A, const float* __restrict__ B, float* __restrict__ C,
    int M, int N, int K, int ldc, long long sA, long long sB, long long sC)
{
    A += (long long)blockIdx.z * sA;
    B += (long long)blockIdx.z * sB;
    C += (long long)blockIdx.z * sC;
    __shared__ uint4 As4[3][2][128];
    __shared__ uint2 Bs2[3][2][64][2];
    const int bm = blockIdx.y * 128, bn = blockIdx.x * 64;
    const int tid = threadIdx.x, lane = tid & 31, warp = tid >> 5;
    const int wm0 = (warp >> 1) * 32, wn0 = (warp & 1) * 32;
    const int fr = lane >> 2, fc = lane & 3;
    const int arow = tid >> 1, ahalf = tid & 1;
    const int brow = tid >> 2, bq = tid & 3;
    const float* Aptr = A + (size_t)(bm + arow) * K + ahalf * 8;
    const float* Bptr = B + (size_t)(bn + brow) * K + bq * 4;
    const unsigned* Aw = (const unsigned*)As4;
    const unsigned* Bw = (const unsigned*)Bs2;
    float acc[2][4][4];
#pragma unroll
    for (int a = 0; a < 2; a++)
#pragma unroll
        for (int b = 0; b < 4; b++)
#pragma unroll
            for (int c = 0; c < 4; c++) acc[a][b][c] = 0.f;

    float4 fA0 = *(const float4*)(Aptr);
    float4 fA1 = *(const float4*)(Aptr + 4);
    float4 fB0 = *(const float4*)(Bptr);

    for (int k0 = 0; k0 < K; k0 += 16) {
        __syncthreads();
        {
            unsigned h0,h1,h2,h3, m0,m1,m2,m3, l0,l1,l2,l3;
            split_pack(fA0.x,fA0.y,h0,m0,l0); split_pack(fA0.z,fA0.w,h1,m1,l1);
            split_pack(fA1.x,fA1.y,h2,m2,l2); split_pack(fA1.z,fA1.w,h3,m3,l3);
            As4[0][ahalf][arow] = make_uint4(h0,h1,h2,h3);
            As4[1][ahalf][arow] = make_uint4(m0,m1,m2,m3);
            As4[2][ahalf][arow] = make_uint4(l0,l1,l2,l3);
            unsigned bh0,bh1,bm0,bm1,bl0,bl1;
            split_pack(fB0.x,fB0.y,bh0,bm0,bl0); split_pack(fB0.z,fB0.w,bh1,bm1,bl1);
            Bs2[0][bq>>1][brow][bq&1] = make_uint2(bh0,bh1);
            Bs2[1][bq>>1][brow][bq&1] = make_uint2(bm0,bm1);
            Bs2[2][bq>>1][brow][bq&1] = make_uint2(bl0,bl1);
        }
        __syncthreads();
        if (k0 + 16 < K) {
            fA0 = *(const float4*)(Aptr + k0 + 16);
            fA1 = *(const float4*)(Aptr + k0 + 20);
            fB0 = *(const float4*)(Bptr + k0 + 16);
        }
        unsigned bfr[4][3][2];
#pragma unroll
        for (int ni = 0; ni < 4; ni++) {
            int rowb = wn0 + ni*8 + fr;
#pragma unroll
            for (int s = 0; s < 3; s++) {
                bfr[ni][s][0] = Bw[((s*2+0)*64 + rowb)*4 + fc];
                bfr[ni][s][1] = Bw[((s*2+1)*64 + rowb)*4 + fc];
            }
        }
#pragma unroll
        for (int mi = 0; mi < 2; mi++) {
            unsigned afr[3][4];
            int ra = wm0 + mi*16;
#pragma unroll
            for (int s = 0; s < 3; s++) {
                afr[s][0] = Aw[((s*2+0)*128 + ra + fr)    *4 + fc];
                afr[s][1] = Aw[((s*2+0)*128 + ra + 8 + fr)*4 + fc];
                afr[s][2] = Aw[((s*2+1)*128 + ra + fr)    *4 + fc];
                afr[s][3] = Aw[((s*2+1)*128 + ra + 8 + fr)*4 + fc];
            }
#pragma unroll
            for (int ni = 0; ni < 4; ni++) {
                MMA_BF16(acc[mi][ni], afr[0], bfr[ni][0]);
                MMA_BF16(acc[mi][ni], afr[0], bfr[ni][1]);
                MMA_BF16(acc[mi][ni], afr[1], bfr[ni][0]);
                MMA_BF16(acc[mi][ni], afr[1], bfr[ni][1]);
                MMA_BF16(acc[mi][ni], afr[0], bfr[ni][2]);
                MMA_BF16(acc[mi][ni], afr[2], bfr[ni][0]);
            }
        }
    }
#pragma unroll
    for (int mi = 0; mi < 2; mi++)
#pragma unroll
        for (int ni = 0; ni < 4; ni++) {
            int row = bm + wm0 + mi*16 + fr;
            int col = bn + wn0 + ni*8 + 2*fc;
            *(float2*)(C + (size_t)row*ldc + col)       = make_float2(acc[mi][ni][0], acc[mi][ni][1]);
            *(float2*)(C + (size_t)(row+8)*ldc + col)   = make_float2(acc[mi][ni][2], acc[mi][ni][3]);
        }
}

// ---------- frozen small kernels ----------
__global__ void gemm_warpdot(const float* __restrict__ A, const float* __restrict__ B,
                             float* __restrict__ C, int M, int N, int K, float scale)
{
    int gw = (int)((blockIdx.x * (size_t)blockDim.x + threadIdx.x) >> 5);
    int lane = threadIdx.x & 31;
    if (gw >= M * N) return;
    int m = gw / N, n = gw % N;
    const float* a = A + (size_t)m * K;
    const float* b = B + (size_t)n * K;
    float s = 0.f;
    for (int k = lane * 4; k < K; k += 128) {
        float4 va = *(const float4*)(a + k);
        float4 vb = *(const float4*)(b + k);
        s += va.x*vb.x + va.y*vb.y + va.z*vb.z + va.w*vb.w;
    }
#pragma unroll
    for (int o = 16; o; o >>= 1) s += __shfl_xor_sync(0xffffffffu, s, o);
    if (lane == 0) C[(size_t)m * N + n] = s * scale;
}

__global__ void rmsnorm_kernel(const float* __restrict__ in, const float* __restrict__ w,
                               float* __restrict__ out, int cols, int in_stride, int out_stride,
                               float eps)
{
    int row = blockIdx.x;
    const float* x = in + (size_t)row * in_stride;
    float* y = out + (size_t)row * out_stride;
    float ss = 0.f;
    for (int i = threadIdx.x; i < cols; i += blockDim.x) { float v = x[i]; ss += v * v; }
    __shared__ float red[32];
    int lane = threadIdx.x & 31, wp = threadIdx.x >> 5;
#pragma unroll
    for (int o = 16; o; o >>= 1) ss += __shfl_xor_sync(0xffffffffu, ss, o);
    if (lane == 0) red[wp] = ss;
    __syncthreads();
    int nw = blockDim.x >> 5;
    float tot = 0.f;
    for (int i = 0; i < nw; i++) tot += red[i];
    float inv = rsqrtf(tot / (float)cols + eps);
    for (int i = threadIdx.x; i < cols; i += blockDim.x) y[i] = x[i] * inv * w[i];
}

__global__ void layernorm128_kernel(float* __restrict__ x, const float* __restrict__ w,
                                    const float* __restrict__ b)
{
    int row = blockIdx.x;
    float* p = x + (size_t)row * DIi;
    int tid = threadIdx.x, lane = tid & 31, wp = tid >> 5;
    float v = p[tid];
    __shared__ float red[4];
    float t = v;
#pragma unroll
    for (int o = 16; o; o >>= 1) t += __shfl_xor_sync(0xffffffffu, t, o);
    if (lane == 0) red[wp] = t;
    __syncthreads();
    float mean = (red[0]+red[1]+red[2]+red[3]) * (1.f/128.f);
    __syncthreads();
    float d = v - mean;
    t = d * d;
#pragma unroll
    for (int o = 16; o; o >>= 1) t += __shfl_xor_sync(0xffffffffu, t, o);
    if (lane == 0) red[wp] = t;
    __syncthreads();
    float var = (red[0]+red[1]+red[2]+red[3]) * (1.f/128.f);
    p[tid] = d * rsqrtf(var + 1e-5f) * w[tid] + b[tid];
}

__global__ void rope_inter_q(float* __restrict__ q, const float* __restrict__ c,
                             const float* __restrict__ sn)
{
    int n = blockIdx.x * blockDim.x + threadIdx.x;
    if (n >= SQ * H * 32) return;
    int s = n / (H*32); int r = n % (H*32); int h = r / 32; int i = r % 32;
    float* p = q + (size_t)s*(H*DQK) + h*DQK + DN + 2*i;
    float x0 = p[0], x1 = p[1];
    float cc = c[s*32+i], ss = sn[s*32+i];
    p[0] = x0*cc - x1*ss; p[1] = x0*ss + x1*cc;
}

__global__ void rope_inter_kpe(const float* __restrict__ kvall, const float* __restrict__ c,
                               const float* __restrict__ sn, float* __restrict__ kpe)
{
    int n = blockIdx.x * blockDim.x + threadIdx.x;
    if (n >= SQ * 32) return;
    int s = n / 32, i = n % 32;
    const float* p = kvall + (size_t)s*(KRr+DRR) + KRr + 2*i;
    float x0 = p[0], x1 = p[1];
    float cc = c[s*32+i], ss = sn[s*32+i];
    kpe[(size_t)s*DRR + 2*i]   = x0*cc - x1*ss;
    kpe[(size_t)s*DRR + 2*i+1] = x0*ss + x1*cc;
}

__global__ void rope_half_qi_kernel(float* __restrict__ qi, const float* __restrict__ c,
                                    const float* __restrict__ sn)
{
    int n = blockIdx.x * blockDim.x + threadIdx.x;
    if (n >= SQ * HIi * 32) return;
    int s = n / (HIi*32); int r = n % (HIi*32); int h = r / 32; int i = r % 32;
    float* p = qi + (size_t)s*(HIi*DIi) + h*DIi;
    float x0 = p[i], x1 = p[i+32];
    float cc = c[s*32+i], ss = sn[s*32+i];
    p[i] = x0*cc - x1*ss; p[i+32] = x0*ss + x1*cc;
}

__global__ void rope_half_ki_kernel(float* __restrict__ ki, const float* __restrict__ c,
                                    const float* __restrict__ sn)
{
    int n = blockIdx.x * blockDim.x + threadIdx.x;
    if (n >= SQ * 32) return;
    int s = n / 32, i = n % 32;
    float* p = ki + (size_t)s*DIi;
    float x0 = p[i], x1 = p[i+32];
    float cc = c[s*32+i], ss = sn[s*32+i];
    p[i] = x0*cc - x1*ss; p[i+32] = x0*ss + x1*cc;
}

// ---------- q absorption (R11 body) ----------
__global__ __launch_bounds__(256) void qabsorb_kernel(
    const float* __restrict__ q, const float* __restrict__ wkvb, float* __restrict__ qabs)
{
    int h = blockIdx.z;
    int s0 = blockIdx.y * 64, c0 = blockIdx.x * 64;
    __shared__ float As[16][68];
    __shared__ float Bs[16][68];
    int tid = threadIdx.x;
    int ts = (tid >> 4) * 4, tc = (tid & 15) * 4;
    ull acc2[4][2];
#pragma unroll
    for (int i = 0; i < 4; i++) { acc2[i][0] = 0ULL; acc2[i][1] = 0ULL; }
    for (int d0 = 0; d0 < 128; d0 += 16) {
        __syncthreads();
        for (int i = tid; i < 1024; i += 256) {
            int r = i >> 4, d = i & 15;
            As[d][r] = q[((size_t)(s0 + r) * H + h) * DQK + d0 + d];
        }
        for (int i = tid; i < 1024; i += 256) {
            int d = i >> 6, c = i & 63;
            Bs[d][c] = wkvb[(size_t)(h * 256 + d0 + d) * KRr + c0 + c];
        }
        __syncthreads();
#pragma unroll
        for (int d = 0; d < 16; d++) {
            float a0 = As[d][ts], a1 = As[d][ts+1], a2 = As[d][ts+2], a3 = As[d][ts+3];
            float4 b = *(float4*)&Bs[d][tc];
            ull b01 = pk2(b.x, b.y), b23 = pk2(b.z, b.w);
            fma2(acc2[0][0], pk2(a0,a0), b01); fma2(acc2[0][1], pk2(a0,a0), b23);
            fma2(acc2[1][0], pk2(a1,a1), b01); fma2(acc2[1][1], pk2(a1,a1), b23);
            fma2(acc2[2][0], pk2(a2,a2), b01); fma2(acc2[2][1], pk2(a2,a2), b23);
            fma2(acc2[3][0], pk2(a3,a3), b01); fma2(acc2[3][1], pk2(a3,a3), b23);
        }
    }
#pragma unroll
    for (int i = 0; i < 4; i++) {
        float2 f01 = upk2(acc2[i][0]), f23 = upk2(acc2[i][1]);
        *(float4*)(qabs + ((size_t)(s0+ts+i) * H + h) * 512 + c0 + tc) =
            make_float4(f01.x, f01.y, f23.x, f23.y);
    }
}

// ---------- indexer (frozen numerics) ----------
__global__ __launch_bounds__(256) void indexer_kernel(
    const float* __restrict__ qi, const float* __restrict__ ki,
    const float* __restrict__ wts, float* __restrict__ iscore)
{
    int t0 = blockIdx.x * 64, s0 = blockIdx.y * 64;
    if (t0 > s0 + 63) return;
    extern __shared__ float dyn[];
    float* kst = dyn;
    float* qs  = dyn + 128*68;
    float* ws  = qs + 64*132;
    int tid = threadIdx.x;
#pragma unroll
    for (int i = 0; i < 8; i++) {
        int lin = i*256 + tid;
        int t = lin >> 5, dq = (lin & 31) * 4;
        float4 kv = *(const float4*)(ki + (size_t)(t0 + t)*DIi + dq);
        kst[(dq+0)*68 + t] = kv.x; kst[(dq+1)*68 + t] = kv.y;
        kst[(dq+2)*68 + t] = kv.z; kst[(dq+3)*68 + t] = kv.w;
    }
    {
        int s = tid >> 2, hg = (tid & 3) * 8;
        float4 w0 = *(const float4*)(wts + (size_t)(s0+s)*HIi + hg);
        float4 w1 = *(const float4*)(wts + (size_t)(s0+s)*HIi + hg + 4);
        float* wp = ws + s*33 + hg;
        wp[0]=w0.x; wp[1]=w0.y; wp[2]=w0.z; wp[3]=w0.w;
        wp[4]=w1.x; wp[5]=w1.y; wp[6]=w1.z; wp[7]=w1.w;
    }
    int si = (tid >> 4) * 4, ti = (tid & 15) * 4;
    int qls = tid >> 2, qld = (tid & 3) * 32;
    float score[4][4];
#pragma unroll
    for (int i = 0; i < 4; i++)
#pragma unroll
        for (int j = 0; j < 4; j++) score[i][j] = 0.f;
    for (int h = 0; h < HIi; h++) {
        __syncthreads();
        const float* qp = qi + (size_t)(s0+qls)*(HIi*DIi) + h*DIi + qld;
#pragma unroll
        for (int j = 0; j < 8; j++)
            *(float4*)&qs[qls*132 + qld + j*4] = *(const float4*)(qp + j*4);
        __syncthreads();
        ull dot2[4][2];
#pragma unroll
        for (int i = 0; i < 4; i++) { dot2[i][0]=0ULL; dot2[i][1]=0ULL; }
#pragma unroll 8
        for (int dd = 0; dd < DIi; dd++) {
            float4 kv = *(const float4*)&kst[dd*68 + ti];
            ull k01 = pk2(kv.x, kv.y), k23 = pk2(kv.z, kv.w);
#pragma unroll
            for (int i = 0; i < 4; i++) {
                float qv = qs[(si+i)*132 + dd];
                ull q2 = pk2(qv, qv);
                fma2(dot2[i][0], q2, k01);
                fma2(dot2[i][1], q2, k23);
            }
        }
#pragma unroll
        for (int i = 0; i < 4; i++) {
            float wv = ws[(si+i)*33 + h];
            float2 d01 = upk2(dot2[i][0]), d23 = upk2(dot2[i][1]);
            score[i][0] += fmaxf(d01.x * INV_SQRT_DI, 0.f) * wv;
            score[i][1] += fmaxf(d01.y * INV_SQRT_DI, 0.f) * wv;
            score[i][2] += fmaxf(d23.x * INV_SQRT_DI, 0.f) * wv;
            score[i][3] += fmaxf(d23.y * INV_SQRT_DI, 0.f) * wv;
        }
    }
#pragma unroll
    for (int i = 0; i < 4; i++) {
        int s = s0 + si + i;
#pragma unroll
        for (int j = 0; j < 4; j++) {
            int t = t0 + ti + j;
            if (t <= s) iscore[(size_t)s*SQ + t] = score[i][j];
        }
    }
}

// ---------- top-512 (frozen) ----------
__device__ __forceinline__ unsigned forder(float f)
{
    unsigned u = __float_as_uint(f);
    return (u & 0x80000000u) ? ~u : (u | 0x80000000u);
}

__global__ __launch_bounds__(256) void topk_kernel(const float* __restrict__ iscore,
                                                   int* __restrict__ tidx, int* __restrict__ tcnt)
{
    int s = blockIdx.x;
    int n = s + 1;
    int tid = threadIdx.x;
    const float* row = iscore + (size_t)s * SQ;
    int* out = tidx + (size_t)s * TOPK;
    if (n <= TOPK) {
        for (int t = tid; t < n; t += 256) out[t] = t;
        if (tid == 0) tcnt[s] = n;
        return;
    }
    __shared__ int hist[256];
    __shared__ unsigned s_pref;
    __shared__ int s_k;
    __shared__ int sc[256];
    if (tid == 0) { s_pref = 0u; s_k = TOPK; }
    __syncthreads();
    for (int pass = 0; pass < 4; pass++) {
        int sh = 24 - 8 * pass;
        unsigned hmask = (pass == 0) ? 0u : (0xFFFFFFFFu << (sh + 8));
        hist[tid] = 0;
        __syncthreads();
        unsigned pref = s_pref;
        for (int t = tid; t < n; t += 256) {
            unsigned u = forder(row[t]);
            if ((u & hmask) == pref) atomicAdd(&hist[(u >> sh) & 255u], 1);
        }
        __syncthreads();
        if (tid == 0) {
            int k = s_k, c = 0, j = 255;
            for (; j >= 0; j--) {
                if (c + hist[j] >= k) break;
                c += hist[j];
            }
            s_k = k - c;
            s_pref = s_pref | ((unsigned)j << sh);
        }
        __syncthreads();
    }
    unsigned uthr = s_pref;
    int kneed = s_k;
    int chunk = (n + 255) / 256;
    int beg = tid * chunk;
    int end = beg + chunk; if (end > n) end = n;
    int cntg = 0, cnte = 0;
    for (int t = beg; t < end; t++) {
        unsigned u = forder(row[t]);
        if (u > uthr) cntg++;
        else if (u == uthr) cnte++;
    }
    sc[tid] = cntg;
    __syncthreads();
    for (int o = 1; o < 256; o <<= 1) {
        int v = (tid >= o) ? sc[tid - o] : 0;
        __syncthreads();
        sc[tid] += v;
        __syncthreads();
    }
    int offg = sc[tid] - cntg;
    int totalg = sc[255];
    __syncthreads();
    sc[tid] = cnte;
    __syncthreads();
    for (int o = 1; o < 256; o <<= 1) {
        int v = (tid >= o) ? sc[tid - o] : 0;
        __syncthreads();
        sc[tid] += v;
        __syncthreads();
    }
    int offe = sc[tid] - cnte;
    for (int t = beg; t < end; t++) {
        unsigned u = forder(row[t]);
        if (u > uthr) {
            out[offg++] = t;
        } else if (u == uthr) {
            int rank = offe++;
            if (rank < kneed) out[totalg + rank] = t;
        }
    }
    if (tid == 0) tcnt[s] = TOPK;
}

// ---------- absorbed attention v3 (R11-measured version) ----------
__global__ __launch_bounds__(256) void attn_v3(
    const float* __restrict__ qabs, const float* __restrict__ q,
    const float* __restrict__ kv, const float* __restrict__ kpe,
    const int* __restrict__ tidx, const int* __restrict__ tcnt,
    float* __restrict__ lat)
{
    int s = blockIdx.x;
    int tid = threadIdx.x, lane = tid & 31, w = tid >> 5;
    int n = tcnt[s];
    extern __shared__ __align__(16) char smraw[];
    ull*   qap = (ull*)smraw;
    float* ps  = (float*)(smraw + 36864);
    ull*   psp = (ull*)(smraw + 36864 + 34816);
    int*   ixs = (int*)(smraw + 36864 + 34816 + 32768);
    ull*   cbuf = (ull*)ps;

    for (int idx = tid; idx < 8*576; idx += 256) {
        int hp = idx / 576, gc = idx - hp*576;
        float f0, f1;
        if (gc < 512) {
            f0 = qabs[((size_t)s*H + 2*hp  )*512 + gc];
            f1 = qabs[((size_t)s*H + 2*hp+1)*512 + gc];
        } else {
            f0 = q[((size_t)s*H + 2*hp  )*DQK + DN + gc - 512];
            f1 = q[((size_t)s*H + 2*hp+1)*DQK + DN + gc - 512];
        }
        qap[idx] = pk2(f0, f1);
    }
    for (int i = tid; i < 512; i += 256) ixs[i] = (i < n) ? tidx[(size_t)s*TOPK + i] : 0;
    __syncthreads();

    int kq = lane >> 3, g8 = lane & 7;
    int nt16 = (n + 15) >> 4;
    for (int T = w; T < nt16; T += 8) {
        int base = T * 16;
        int r0 = ixs[base + kq*4 + 0], r1 = ixs[base + kq*4 + 1];
        int r2 = ixs[base + kq*4 + 2], r3 = ixs[base + kq*4 + 3];
        ull acc[4][8];
#pragma unroll
        for (int i = 0; i < 4; i++)
#pragma unroll
            for (int hp = 0; hp < 8; hp++) acc[i][hp] = 0ULL;
#pragma unroll 4
        for (int st = 0; st < 16; st++) {
            int g = g8 + 8*st;
            float4 k0 = *(const float4*)(kv + (size_t)r0*KRr + g*4);
            float4 k1 = *(const float4*)(kv + (size_t)r1*KRr + g*4);
            float4 k2 = *(const float4*)(kv + (size_t)r2*KRr + g*4);
            float4 k3 = *(const float4*)(kv + (size_t)r3*KRr + g*4);
#pragma unroll
            for (int c = 0; c < 4; c++) {
                float c0 = ((const float*)&k0)[c], c1 = ((const float*)&k1)[c];
                float c2 = ((const float*)&k2)[c], c3 = ((const float*)&k3)[c];
                ull p0 = pk2(c0,c0), p1 = pk2(c1,c1), p2 = pk2(c2,c2), p3 = pk2(c3,c3);
#pragma unroll
                for (int hp = 0; hp < 8; hp++) {
                    ull qa = qap[hp*576 + 4*g + c];
                    fma2(acc[0][hp], p0, qa);
                    fma2(acc[1][hp], p1, qa);
                    fma2(acc[2][hp], p2, qa);
                    fma2(acc[3][hp], p3, qa);
                }
            }
        }
#pragma unroll
        for (int st = 16; st < 18; st++) {
            int g = g8 + 8*st;
            float4 k0 = *(const float4*)(kpe + (size_t)r0*DRR + (g-128)*4);
            float4 k1 = *(const float4*)(kpe + (size_t)r1*DRR + (g-128)*4);
            float4 k2 = *(const float4*)(kpe + (size_t)r2*DRR + (g-128)*4);
            float4 k3 = *(const float4*)(kpe + (size_t)r3*DRR + (g-128)*4);
#pragma unroll
            for (int c = 0; c < 4; c++) {
                float c0 = ((const float*)&k0)[c], c1 = ((const float*)&k1)[c];
                float c2 = ((const float*)&k2)[c], c3 = ((const float*)&k3)[c];
                ull p0 = pk2(c0,c0), p1 = pk2(c1,c1), p2 = pk2(c2,c2), p3 = pk2(c3,c3);
#pragma unroll
                for (int hp = 0; hp < 8; hp++) {
                    ull qa = qap[hp*576 + 4*g + c];
                    fma2(acc[0][hp], p0, qa);
                    fma2(acc[1][hp], p1, qa);
                    fma2(acc[2][hp], p2, qa);
                    fma2(acc[3][hp], p3, qa);
                }
            }
        }
#pragma unroll
        for (int i = 0; i < 4; i++)
#pragma unroll
            for (int hp = 0; hp < 8; hp++) {
                ull v = acc[i][hp];
                v = add2(v, __shfl_xor_sync(0xffffffffu, v, 1));
                v = add2(v, __shfl_xor_sync(0xffffffffu, v, 2));
                v = add2(v, __shfl_xor_sync(0xffffffffu, v, 4));
                acc[i][hp] = v;
            }
        if (g8 == 0) {
#pragma unroll
            for (int i = 0; i < 4; i++) {
                int j = base + kq*4 + i;
#pragma unroll
                for (int hp = 0; hp < 8; hp++) {
                    float2 f = upk2(acc[i][hp]);
                    ps[j*17 + 2*hp]     = f.x * INV_SQRT_DQK;
                    ps[j*17 + 2*hp + 1] = f.y * INV_SQRT_DQK;
                }
            }
        }
    }
    __syncthreads();

    for (int h = 2*w; h < 2*w + 2; h++) {
        float m = -FLT_MAX;
        for (int j = lane; j < n; j += 32) m = fmaxf(m, ps[j*17 + h]);
#pragma unroll
        for (int o = 16; o; o >>= 1) m = fmaxf(m, __shfl_xor_sync(0xffffffffu, m, o));
        float ssum = 0.f;
        for (int j = lane; j < n; j += 32) {
            float e = __expf(ps[j*17 + h] - m);
            ps[j*17 + h] = e; ssum += e;
        }
#pragma unroll
        for (int o = 16; o; o >>= 1) ssum += __shfl_xor_sync(0xffffffffu, ssum, o);
        float inv = 1.f / ssum;
        for (int j = lane; j < n; j += 32) ps[j*17 + h] *= inv;
        for (int j = n + lane; j < 512; j += 32) ps[j*17 + h] = 0.f;
    }
    __syncthreads();

    for (int idx = tid; idx < 4096; idx += 256) {
        int j = idx >> 3, hp = idx & 7;
        psp[idx] = pk2(ps[j*17 + 2*hp], ps[j*17 + 2*hp + 1]);
    }
    __syncthreads();

    int gq = w & 3, par = w >> 2;
    int gran = gq * 32 + lane;
    ull acc2[32];
#pragma unroll
    for (int i = 0; i < 32; i++) acc2[i] = 0ULL;
    for (int j = par; j < n; j += 2) {
        int row = ixs[j];
        float4 v4 = *(const float4*)(kv + (size_t)row * KRr + gran * 4);
        ull c0 = pk2(v4.x,v4.x), c1 = pk2(v4.y,v4.y), c2 = pk2(v4.z,v4.z), c3 = pk2(v4.w,v4.w);
        const ull* pr = psp + j*8;
#pragma unroll
        for (int hp = 0; hp < 8; hp++) {
            ull p = pr[hp];
            fma2(acc2[hp*4+0], c0, p);
            fma2(acc2[hp*4+1], c1, p);
            fma2(acc2[hp*4+2], c2, p);
            fma2(acc2[hp*4+3], c3, p);
        }
    }
    if (par == 1) {
#pragma unroll
        for (int k = 0; k < 32; k++) cbuf[k*128 + gran] = acc2[k];
    }
    __syncthreads();
    if (par == 0) {
#pragma unroll
        for (int k = 0; k < 32; k++) acc2[k] = add2(acc2[k], cbuf[k*128 + gran]);
#pragma unroll
        for (int hp = 0; hp < 8; hp++) {
            float2 u0 = upk2(acc2[hp*4+0]), u1 = upk2(acc2[hp*4+1]);
            float2 u2 = upk2(acc2[hp*4+2]), u3 = upk2(acc2[hp*4+3]);
            *(float4*)(lat + ((size_t)(2*hp  )*SQ + s)*512 + gran*4) = make_float4(u0.x,u1.x,u2.x,u3.x);
            *(float4*)(lat + ((size_t)(2*hp+1)*SQ + s)*512 + gran*4) = make_float4(u0.y,u1.y,u2.y,u3.y);
        }
    }
}

// ---------- host ----------
extern "C" void kernel_launch(void* const* d_in, const int* in_sizes, int n_in,
                              void* d_out, int out_size)
{
    const float *hidden, *cosp, *sinp, *wq_a, *q_norm_w, *wq_b, *wkv_a, *kv_norm_w,
                *wkv_b, *wo, *idx_wq_b, *idx_wk, *idx_kn_w, *idx_kn_b, *idx_wproj;
    if (n_in >= 2 && in_sizes[1] == 3145728) {
        hidden=(const float*)d_in[0];  wq_a=(const float*)d_in[1];
        q_norm_w=(const float*)d_in[2]; wq_b=(const float*)d_in[3];
        wkv_a=(const float*)d_in[4];   kv_norm_w=(const float*)d_in[5];
        wkv_b=(const float*)d_in[6];   wo=(const float*)d_in[7];
        idx_wq_b=(const float*)d_in[8]; idx_wk=(const float*)d_in[9];
        idx_kn_w=(const float*)d_in[10]; idx_kn_b=(const float*)d_in[11];
        idx_wproj=(const float*)d_in[12]; cosp=(const float*)d_in[13];
        sinp=(const float*)d_in[14];
    } else {
        hidden=(const float*)d_in[0];  cosp=(const float*)d_in[1];
        sinp=(const float*)d_in[2];    wq_a=(const float*)d_in[4];
        q_norm_w=(const float*)d_in[5]; wq_b=(const float*)d_in[6];
        wkv_a=(const float*)d_in[7];   kv_norm_w=(const float*)d_in[8];
        wkv_b=(const float*)d_in[9];   wo=(const float*)d_in[10];
        idx_wq_b=(const float*)d_in[11]; idx_wk=(const float*)d_in[12];
        idx_kn_w=(const float*)d_in[13]; idx_kn_b=(const float*)d_in[14];
        idx_wproj=(const float*)d_in[15];
    }
    float *qr, *q, *kvall, *kv, *kpe, *qi, *ki, *wtsb, *iscore, *qabs, *lat, *attnb;
    int *tix, *tcn;
    cudaGetSymbolAddress((void**)&qr, g_qr);
    cudaGetSymbolAddress((void**)&q, g_q);
    cudaGetSymbolAddress((void**)&kvall, g_kvall);
    cudaGetSymbolAddress((void**)&kv, g_kv);
    cudaGetSymbolAddress((void**)&kpe, g_kpe);
    cudaGetSymbolAddress((void**)&qi, g_qi);
    cudaGetSymbolAddress((void**)&ki, g_ki);
    cudaGetSymbolAddress((void**)&wtsb, g_wts);
    cudaGetSymbolAddress((void**)&iscore, g_iscore);
    cudaGetSymbolAddress((void**)&qabs, g_qabs);
    cudaGetSymbolAddress((void**)&lat, g_lat);
    cudaGetSymbolAddress((void**)&attnb, g_attn);
    cudaGetSymbolAddress((void**)&tix, g_tidx);
    cudaGetSymbolAddress((void**)&tcn, g_tcnt);

    const int ISMEM = (128*68 + 64*132 + 64*33) * 4;
    cudaFuncSetAttribute(indexer_kernel, cudaFuncAttributeMaxDynamicSharedMemorySize, ISMEM);
    const int ASMEM = 36864 + 34816 + 32768 + 2048;   // 106496
    cudaFuncSetAttribute(attn_v3, cudaFuncAttributeMaxDynamicSharedMemorySize, ASMEM);

    // ---- frozen indexer path ----
    sgemm_nt<<<dim3(16, 12), 256>>>(hidden, wq_a, qr, SQ, QRr, DM);
    rmsnorm_kernel<<<SQ, 256>>>(qr, q_norm_w, qr, QRr, QRr, QRr, 1e-6f);
    sgemm_nt<<<dim3(16, 32), 256>>>(qr, idx_wq_b, qi, SQ, HIi*DIi, QRr);
    rope_half_qi_kernel<<<(SQ*HIi*32 + 255)/256, 256>>>(qi, cosp, sinp);
    gemm_warpdot<<<(SQ*DIi*32)/256, 256>>>(hidden, idx_wk, ki, SQ, DIi, DM, 1.f);
    layernorm128_kernel<<<SQ, 128>>>(ki, idx_kn_w, idx_kn_b);
    rope_half_ki_kernel<<<(SQ*32 + 255)/256, 256>>>(ki, cosp, sinp);
    gemm_warpdot<<<(SQ*HIi*32)/256, 256>>>(hidden, idx_wproj, wtsb, SQ, HIi, DM, INV_SQRT_HI);

    // ---- value path ----
    gemm_bf16x6<<<dim3((H*DQK)/64, 16), 256>>>(qr, wq_b, q, SQ, H*DQK, QRr, H*DQK, 0, 0, 0);
    rope_inter_q<<<(SQ*H*32 + 255)/256, 256>>>(q, cosp, sinp);
    gemm_bf16x6<<<dim3((KRr+DRR)/64, 16), 256>>>(hidden, wkv_a, kvall, SQ, KRr+DRR, DM, KRr+DRR, 0, 0, 0);
    rmsnorm_kernel<<<SQ, 256>>>(kvall, kv_norm_w, kv, KRr, KRr+DRR, KRr, 1e-6f);
    rope_inter_kpe<<<(SQ*32 + 255)/256, 256>>>(kvall, cosp, sinp, kpe);
    qabsorb_kernel<<<dim3(8, 32, 16), 256>>>(q, wkv_b, qabs);

    // ---- selection ----
    indexer_kernel<<<dim3(32, 32), 256, ISMEM>>>(qi, ki, wtsb, iscore);
    topk_kernel<<<SQ, 256>>>(iscore, tix, tcn);

    // ---- absorbed attention ----
    attn_v3<<<SQ, 256, ASMEM>>>(qabs, q, kv, kpe, tix, tcn, lat);

    // latent -> per-head values
    gemm_bf16x6<<<dim3(2, 16, 16), 256>>>(lat, wkv_b + (size_t)DN*KRr, attnb,
                                          SQ, DV, KRr, H*DV,
                                          (long long)SQ*KRr, (long long)(DN+DV)*KRr, DV);
    // output projection
    gemm_bf16x6<<<dim3(32, 16, 1), 256>>>(attnb, wo, (float*)d_out, SQ, DM, DM, DM, 0, 0, 0);
}

// round 15
// speedup vs baseline: 1.0420x; 1.0420x over previous
#include <cuda_runtime.h>
#include <cuda_bf16.h>
#include <math.h>
#include <float.h>
#include <stdint.h>
typedef unsigned long long ull;

#define SQ   2048
#define DM   2048
#define H    16
#define DN   128
#define DRR  64
#define DV   128
#define QRr  1536
#define KRr  512
#define HIi  32
#define DIi  128
#define TOPK 512
#define DQK  192
#define INV_SQRT_DQK 0.07216878364870322f
#define INV_SQRT_DI  0.08838834764831845f
#define INV_SQRT_HI  0.17677669529663687f

__device__ float g_qr   [SQ * QRr];
__device__ float g_q    [SQ * H * DQK];
__device__ float g_kvall[SQ * (KRr + DRR)];
__device__ float g_kv   [SQ * KRr];
__device__ float g_kpe  [SQ * DRR];
__device__ float g_qi   [SQ * HIi * DIi];
__device__ float g_ki   [SQ * DIi];
__device__ float g_wts  [SQ * HIi];
__device__ float g_iscore[(size_t)SQ * SQ];
__device__ int   g_tidx [SQ * TOPK];
__device__ int   g_tcnt [SQ];
__device__ float g_qabs [(size_t)SQ * H * 512];
__device__ float g_lat  [(size_t)H * SQ * 512];
__device__ float g_attn [SQ * H * DV];

__device__ __forceinline__ ull pk2(float x, float y)
{ ull r; asm("mov.b64 %0, {%1, %2};" : "=l"(r) : "f"(x), "f"(y)); return r; }
__device__ __forceinline__ void fma2(ull &c, ull a, ull b)
{ asm("fma.rn.f32x2 %0, %1, %2, %0;" : "+l"(c) : "l"(a), "l"(b)); }
__device__ __forceinline__ float2 upk2(ull v)
{ float2 f; asm("mov.b64 {%0, %1}, %2;" : "=f"(f.x), "=f"(f.y) : "l"(v)); return f; }
__device__ __forceinline__ ull add2(ull a, ull b)
{ ull r; asm("add.rn.f32x2 %0, %1, %2;" : "=l"(r) : "l"(a), "l"(b)); return r; }

// ---------- SGEMM fp32x2 (frozen numerics; indexer path) ----------
__global__ __launch_bounds__(256) void sgemm_nt(
    const float* __restrict__ A, const float* __restrict__ B, float* __restrict__ C,
    int M, int N, int K)
{
    __shared__ float As[16][128];
    __shared__ float Bs[16][128];
    const int bm = blockIdx.x * 128, bn = blockIdx.y * 128;
    const int tid = threadIdx.x;
    const int lr = tid >> 2, lc = (tid & 3) << 2;
    const int tm = (tid >> 4) << 3, tn = (tid & 15) << 3;
    ull acc2[8][4];
#pragma unroll
    for (int i = 0; i < 8; i++)
#pragma unroll
        for (int j = 0; j < 4; j++) acc2[i][j] = 0ULL;
    for (int k0 = 0; k0 < K; k0 += 16) {
#pragma unroll
        for (int i = 0; i < 2; i++) {
            int r = lr + i * 64;
            float4 va = make_float4(0.f,0.f,0.f,0.f), vb = make_float4(0.f,0.f,0.f,0.f);
            if (bm + r < M) va = *(const float4*)(A + (size_t)(bm + r) * K + k0 + lc);
            if (bn + r < N) vb = *(const float4*)(B + (size_t)(bn + r) * K + k0 + lc);
            As[lc+0][r]=va.x; As[lc+1][r]=va.y; As[lc+2][r]=va.z; As[lc+3][r]=va.w;
            Bs[lc+0][r]=vb.x; Bs[lc+1][r]=vb.y; Bs[lc+2][r]=vb.z; Bs[lc+3][r]=vb.w;
        }
        __syncthreads();
#pragma unroll
        for (int kk = 0; kk < 16; kk++) {
            float a[8], b[8];
#pragma unroll
            for (int i = 0; i < 8; i++) a[i] = As[kk][tm + i];
#pragma unroll
            for (int j = 0; j < 8; j++) b[j] = Bs[kk][tn + j];
            ull b2[4];
#pragma unroll
            for (int j = 0; j < 4; j++) b2[j] = pk2(b[2*j], b[2*j+1]);
#pragma unroll
            for (int i = 0; i < 8; i++) {
                ull a2 = pk2(a[i], a[i]);
#pragma unroll
                for (int j = 0; j < 4; j++) fma2(acc2[i][j], a2, b2[j]);
            }
        }
        __syncthreads();
    }
#pragma unroll
    for (int i = 0; i < 8; i++) {
        int m = bm + tm + i;
        if (m >= M) continue;
#pragma unroll
        for (int j = 0; j < 4; j++) {
            float2 f = upk2(acc2[i][j]);
            int n = bn + tn + 2*j;
            if (n < N)     C[(size_t)m*N + n]     = f.x;
            if (n+1 < N)   C[(size_t)m*N + n + 1] = f.y;
        }
    }
}

// ---------- bf16x6 tensor GEMM (smooth path), batched ----------
__device__ __forceinline__ void split_pack(float x, float y,
                                           unsigned &ph, unsigned &pm, unsigned &pl)
{
    __nv_bfloat16 hx = __float2bfloat16(x);
    float rx = x - __bfloat162float(hx);
    __nv_bfloat16 mx = __float2bfloat16(rx);
    __nv_bfloat16 lx = __float2bfloat16(rx - __bfloat162float(mx));
    __nv_bfloat16 hy = __float2bfloat16(y);
    float ry = y - __bfloat162float(hy);
    __nv_bfloat16 my = __float2bfloat16(ry);
    __nv_bfloat16 ly = __float2bfloat16(ry - __bfloat162float(my));
    ph = (unsigned)__bfloat16_as_ushort(hx) | ((unsigned)__bfloat16_as_ushort(hy) << 16);
    pm = (unsigned)__bfloat16_as_ushort(mx) | ((unsigned)__bfloat16_as_ushort(my) << 16);
    pl = (unsigned)__bfloat16_as_ushort(lx) | ((unsigned)__bfloat16_as_ushort(ly) << 16);
}

#define MMA_BF16(cc, aa, bb)                                                     \
    asm volatile(                                                                \
        "mma.sync.aligned.m16n8k16.row.col.f32.bf16.bf16.f32 "                   \
        "{%0,%1,%2,%3},{%4,%5,%6,%7},{%8,%9},{%0,%1,%2,%3};\n"                   \
        : "+f"((cc)[0]), "+f"((cc)[1]), "+f"((cc)[2]), "+f"((cc)[3])             \
        : "r"((aa)[0]), "r"((aa)[1]), "r"((aa)[2]), "r"((aa)[3]),                \
          "r"((bb)[0]), "r"((bb)[1]))

__global__ __launch_bounds__(256) void gemm_bf16x6(
    const float* __restrict__ A, const float* __restrict__ B, float* __restrict__ C,
    int M, int N, int K, int ldc, long long sA, long long sB, long long sC)
{
    A += (long long)blockIdx.z * sA;
    B += (long long)blockIdx.z * sB;
    C += (long long)blockIdx.z * sC;
    __shared__ uint4 As4[3][2][128];
    __shared__ uint2 Bs2[3][2][64][2];
    const int bm = blockIdx.y * 128, bn = blockIdx.x * 64;
    const int tid = threadIdx.x, lane = tid & 31, warp = tid >> 5;
    const int wm0 = (warp >> 1) * 32, wn0 = (warp & 1) * 32;
    const int fr = lane >> 2, fc = lane & 3;
    const int arow = tid >> 1, ahalf = tid & 1;
    const int brow = tid >> 2, bq = tid & 3;
    const float* Aptr = A + (size_t)(bm + arow) * K + ahalf * 8;
    const float* Bptr = B + (size_t)(bn + brow) * K + bq * 4;
    const unsigned* Aw = (const unsigned*)As4;
    const unsigned* Bw = (const unsigned*)Bs2;
    float acc[2][4][4];
#pragma unroll
    for (int a = 0; a < 2; a++)
#pragma unroll
        for (int b = 0; b < 4; b++)
#pragma unroll
            for (int c = 0; c < 4; c++) acc[a][b][c] = 0.f;
    for (int k0 = 0; k0 < K; k0 += 16) {
        __syncthreads();
        {
            float4 f0 = *(const float4*)(Aptr + k0);
            float4 f1 = *(const float4*)(Aptr + k0 + 4);
            unsigned h0,h1,h2,h3, m0,m1,m2,m3, l0,l1,l2,l3;
            split_pack(f0.x,f0.y,h0,m0,l0); split_pack(f0.z,f0.w,h1,m1,l1);
            split_pack(f1.x,f1.y,h2,m2,l2); split_pack(f1.z,f1.w,h3,m3,l3);
            As4[0][ahalf][arow] = make_uint4(h0,h1,h2,h3);
            As4[1][ahalf][arow] = make_uint4(m0,m1,m2,m3);
            As4[2][ahalf][arow] = make_uint4(l0,l1,l2,l3);
        }
        {
            float4 f0 = *(const float4*)(Bptr + k0);
            unsigned bh0,bh1,bm0,bm1,bl0,bl1;
            split_pack(f0.x,f0.y,bh0,bm0,bl0); split_pack(f0.z,f0.w,bh1,bm1,bl1);
            Bs2[0][bq>>1][brow][bq&1] = make_uint2(bh0,bh1);
            Bs2[1][bq>>1][brow][bq&1] = make_uint2(bm0,bm1);
            Bs2[2][bq>>1][brow][bq&1] = make_uint2(bl0,bl1);
        }
        __syncthreads();
        unsigned bfr[4][3][2];
#pragma unroll
        for (int ni = 0; ni < 4; ni++) {
            int rowb = wn0 + ni*8 + fr;
#pragma unroll
            for (int s = 0; s < 3; s++) {
                bfr[ni][s][0] = Bw[((s*2+0)*64 + rowb)*4 + fc];
                bfr[ni][s][1] = Bw[((s*2+1)*64 + rowb)*4 + fc];
            }
        }
#pragma unroll
        for (int mi = 0; mi < 2; mi++) {
            unsigned afr[3][4];
            int ra = wm0 + mi*16;
#pragma unroll
            for (int s = 0; s < 3; s++) {
                afr[s][0] = Aw[((s*2+0)*128 + ra + fr)    *4 + fc];
                afr[s][1] = Aw[((s*2+0)*128 + ra + 8 + fr)*4 + fc];
                afr[s][2] = Aw[((s*2+1)*128 + ra + fr)    *4 + fc];
                afr[s][3] = Aw[((s*2+1)*128 + ra + 8 + fr)*4 + fc];
            }
#pragma unroll
            for (int ni = 0; ni < 4; ni++) {
                MMA_BF16(acc[mi][ni], afr[0], bfr[ni][0]);
                MMA_BF16(acc[mi][ni], afr[0], bfr[ni][1]);
                MMA_BF16(acc[mi][ni], afr[1], bfr[ni][0]);
                MMA_BF16(acc[mi][ni], afr[1], bfr[ni][1]);
                MMA_BF16(acc[mi][ni], afr[0], bfr[ni][2]);
                MMA_BF16(acc[mi][ni], afr[2], bfr[ni][0]);
            }
        }
    }
#pragma unroll
    for (int mi = 0; mi < 2; mi++)
#pragma unroll
        for (int ni = 0; ni < 4; ni++) {
            int row = bm + wm0 + mi*16 + fr;
            int col = bn + wn0 + ni*8 + 2*fc;
            *(float2*)(C + (size_t)row*ldc + col)       = make_float2(acc[mi][ni][0], acc[mi][ni][1]);
            *(float2*)(C + (size_t)(row+8)*ldc + col)   = make_float2(acc[mi][ni][2], acc[mi][ni][3]);
        }
}

// ---------- frozen small kernels ----------
__global__ void gemm_warpdot(const float* __restrict__ A, const float* __restrict__ B,
                             float* __restrict__ C, int M, int N, int K, float scale)
{
    int gw = (int)((blockIdx.x * (size_t)blockDim.x + threadIdx.x) >> 5);
    int lane = threadIdx.x & 31;
    if (gw >= M * N) return;
    int m = gw / N, n = gw % N;
    const float* a = A + (size_t)m * K;
    const float* b = B + (size_t)n * K;
    float s = 0.f;
    for (int k = lane * 4; k < K; k += 128) {
        float4 va = *(const float4*)(a + k);
        float4 vb = *(const float4*)(b + k);
        s += va.x*vb.x + va.y*vb.y + va.z*vb.z + va.w*vb.w;
    }
#pragma unroll
    for (int o = 16; o; o >>= 1) s += __shfl_xor_sync(0xffffffffu, s, o);
    if (lane == 0) C[(size_t)m * N + n] = s * scale;
}

__global__ void rmsnorm_kernel(const float* __restrict__ in, const float* __restrict__ w,
                               float* __restrict__ out, int cols, int in_stride, int out_stride,
                               float eps)
{
    int row = blockIdx.x;
    const float* x = in + (size_t)row * in_stride;
    float* y = out + (size_t)row * out_stride;
    float ss = 0.f;
    for (int i = threadIdx.x; i < cols; i += blockDim.x) { float v = x[i]; ss += v * v; }
    __shared__ float red[32];
    int lane = threadIdx.x & 31, wp = threadIdx.x >> 5;
#pragma unroll
    for (int o = 16; o; o >>= 1) ss += __shfl_xor_sync(0xffffffffu, ss, o);
    if (lane == 0) red[wp] = ss;
    __syncthreads();
    int nw = blockDim.x >> 5;
    float tot = 0.f;
    for (int i = 0; i < nw; i++) tot += red[i];
    float inv = rsqrtf(tot / (float)cols + eps);
    for (int i = threadIdx.x; i < cols; i += blockDim.x) y[i] = x[i] * inv * w[i];
}

__global__ void layernorm128_kernel(float* __restrict__ x, const float* __restrict__ w,
                                    const float* __restrict__ b)
{
    int row = blockIdx.x;
    float* p = x + (size_t)row * DIi;
    int tid = threadIdx.x, lane = tid & 31, wp = tid >> 5;
    float v = p[tid];
    __shared__ float red[4];
    float t = v;
#pragma unroll
    for (int o = 16; o; o >>= 1) t += __shfl_xor_sync(0xffffffffu, t, o);
    if (lane == 0) red[wp] = t;
    __syncthreads();
    float mean = (red[0]+red[1]+red[2]+red[3]) * (1.f/128.f);
    __syncthreads();
    float d = v - mean;
    t = d * d;
#pragma unroll
    for (int o = 16; o; o >>= 1) t += __shfl_xor_sync(0xffffffffu, t, o);
    if (lane == 0) red[wp] = t;
    __syncthreads();
    float var = (red[0]+red[1]+red[2]+red[3]) * (1.f/128.f);
    p[tid] = d * rsqrtf(var + 1e-5f) * w[tid] + b[tid];
}

__global__ void rope_inter_q(float* __restrict__ q, const float* __restrict__ c,
                             const float* __restrict__ sn)
{
    int n = blockIdx.x * blockDim.x + threadIdx.x;
    if (n >= SQ * H * 32) return;
    int s = n / (H*32); int r = n % (H*32); int h = r / 32; int i = r % 32;
    float* p = q + (size_t)s*(H*DQK) + h*DQK + DN + 2*i;
    float x0 = p[0], x1 = p[1];
    float cc = c[s*32+i], ss = sn[s*32+i];
    p[0] = x0*cc - x1*ss; p[1] = x0*ss + x1*cc;
}

__global__ void rope_inter_kpe(const float* __restrict__ kvall, const float* __restrict__ c,
                               const float* __restrict__ sn, float* __restrict__ kpe)
{
    int n = blockIdx.x * blockDim.x + threadIdx.x;
    if (n >= SQ * 32) return;
    int s = n / 32, i = n % 32;
    const float* p = kvall + (size_t)s*(KRr+DRR) + KRr + 2*i;
    float x0 = p[0], x1 = p[1];
    float cc = c[s*32+i], ss = sn[s*32+i];
    kpe[(size_t)s*DRR + 2*i]   = x0*cc - x1*ss;
    kpe[(size_t)s*DRR + 2*i+1] = x0*ss + x1*cc;
}

__global__ void rope_half_qi_kernel(float* __restrict__ qi, const float* __restrict__ c,
                                    const float* __restrict__ sn)
{
    int n = blockIdx.x * blockDim.x + threadIdx.x;
    if (n >= SQ * HIi * 32) return;
    int s = n / (HIi*32); int r = n % (HIi*32); int h = r / 32; int i = r % 32;
    float* p = qi + (size_t)s*(HIi*DIi) + h*DIi;
    float x0 = p[i], x1 = p[i+32];
    float cc = c[s*32+i], ss = sn[s*32+i];
    p[i] = x0*cc - x1*ss; p[i+32] = x0*ss + x1*cc;
}

__global__ void rope_half_ki_kernel(float* __restrict__ ki, const float* __restrict__ c,
                                    const float* __restrict__ sn)
{
    int n = blockIdx.x * blockDim.x + threadIdx.x;
    if (n >= SQ * 32) return;
    int s = n / 32, i = n % 32;
    float* p = ki + (size_t)s*DIi;
    float x0 = p[i], x1 = p[i+32];
    float cc = c[s*32+i], ss = sn[s*32+i];
    p[i] = x0*cc - x1*ss; p[i+32] = x0*ss + x1*cc;
}

// ---------- q absorption ----------
__global__ __launch_bounds__(256) void qabsorb_kernel(
    const float* __restrict__ q, const float* __restrict__ wkvb, float* __restrict__ qabs)
{
    int h = blockIdx.z;
    int s0 = blockIdx.y * 64, c0 = blockIdx.x * 64;
    __shared__ float As[16][68];
    __shared__ float Bs[16][68];
    int tid = threadIdx.x;
    int ts = (tid >> 4) * 4, tc = (tid & 15) * 4;
    ull acc2[4][2];
#pragma unroll
    for (int i = 0; i < 4; i++) { acc2[i][0] = 0ULL; acc2[i][1] = 0ULL; }
    for (int d0 = 0; d0 < 128; d0 += 16) {
        __syncthreads();
        for (int i = tid; i < 1024; i += 256) {
            int r = i >> 4, d = i & 15;
            As[d][r] = q[((size_t)(s0 + r) * H + h) * DQK + d0 + d];
        }
        for (int i = tid; i < 1024; i += 256) {
            int d = i >> 6, c = i & 63;
            Bs[d][c] = wkvb[(size_t)(h * 256 + d0 + d) * KRr + c0 + c];
        }
        __syncthreads();
#pragma unroll
        for (int d = 0; d < 16; d++) {
            float a0 = As[d][ts], a1 = As[d][ts+1], a2 = As[d][ts+2], a3 = As[d][ts+3];
            float4 b = *(float4*)&Bs[d][tc];
            ull b01 = pk2(b.x, b.y), b23 = pk2(b.z, b.w);
            fma2(acc2[0][0], pk2(a0,a0), b01); fma2(acc2[0][1], pk2(a0,a0), b23);
            fma2(acc2[1][0], pk2(a1,a1), b01); fma2(acc2[1][1], pk2(a1,a1), b23);
            fma2(acc2[2][0], pk2(a2,a2), b01); fma2(acc2[2][1], pk2(a2,a2), b23);
            fma2(acc2[3][0], pk2(a3,a3), b01); fma2(acc2[3][1], pk2(a3,a3), b23);
        }
    }
#pragma unroll
    for (int i = 0; i < 4; i++) {
        float2 f01 = upk2(acc2[i][0]), f23 = upk2(acc2[i][1]);
        *(float4*)(qabs + ((size_t)(s0+ts+i) * H + h) * 512 + c0 + tc) =
            make_float4(f01.x, f01.y, f23.x, f23.y);
    }
}

// ---------- indexer (frozen numerics) ----------
__global__ __launch_bounds__(256) void indexer_kernel(
    const float* __restrict__ qi, const float* __restrict__ ki,
    const float* __restrict__ wts, float* __restrict__ iscore)
{
    int t0 = blockIdx.x * 64, s0 = blockIdx.y * 64;
    if (t0 > s0 + 63) return;
    extern __shared__ float dyn[];
    float* kst = dyn;
    float* qs  = dyn + 128*68;
    float* ws  = qs + 64*132;
    int tid = threadIdx.x;
#pragma unroll
    for (int i = 0; i < 8; i++) {
        int lin = i*256 + tid;
        int t = lin >> 5, dq = (lin & 31) * 4;
        float4 kv = *(const float4*)(ki + (size_t)(t0 + t)*DIi + dq);
        kst[(dq+0)*68 + t] = kv.x; kst[(dq+1)*68 + t] = kv.y;
        kst[(dq+2)*68 + t] = kv.z; kst[(dq+3)*68 + t] = kv.w;
    }
    {
        int s = tid >> 2, hg = (tid & 3) * 8;
        float4 w0 = *(const float4*)(wts + (size_t)(s0+s)*HIi + hg);
        float4 w1 = *(const float4*)(wts + (size_t)(s0+s)*HIi + hg + 4);
        float* wp = ws + s*33 + hg;
        wp[0]=w0.x; wp[1]=w0.y; wp[2]=w0.z; wp[3]=w0.w;
        wp[4]=w1.x; wp[5]=w1.y; wp[6]=w1.z; wp[7]=w1.w;
    }
    int si = (tid >> 4) * 4, ti = (tid & 15) * 4;
    int qls = tid >> 2, qld = (tid & 3) * 32;
    float score[4][4];
#pragma unroll
    for (int i = 0; i < 4; i++)
#pragma unroll
        for (int j = 0; j < 4; j++) score[i][j] = 0.f;
    for (int h = 0; h < HIi; h++) {
        __syncthreads();
        const float* qp = qi + (size_t)(s0+qls)*(HIi*DIi) + h*DIi + qld;
#pragma unroll
        for (int j = 0; j < 8; j++)
            *(float4*)&qs[qls*132 + qld + j*4] = *(const float4*)(qp + j*4);
        __syncthreads();
        ull dot2[4][2];
#pragma unroll
        for (int i = 0; i < 4; i++) { dot2[i][0]=0ULL; dot2[i][1]=0ULL; }
#pragma unroll 8
        for (int dd = 0; dd < DIi; dd++) {
            float4 kv = *(const float4*)&kst[dd*68 + ti];
            ull k01 = pk2(kv.x, kv.y), k23 = pk2(kv.z, kv.w);
#pragma unroll
            for (int i = 0; i < 4; i++) {
                float qv = qs[(si+i)*132 + dd];
                ull q2 = pk2(qv, qv);
                fma2(dot2[i][0], q2, k01);
                fma2(dot2[i][1], q2, k23);
            }
        }
#pragma unroll
        for (int i = 0; i < 4; i++) {
            float wv = ws[(si+i)*33 + h];
            float2 d01 = upk2(dot2[i][0]), d23 = upk2(dot2[i][1]);
            score[i][0] += fmaxf(d01.x * INV_SQRT_DI, 0.f) * wv;
            score[i][1] += fmaxf(d01.y * INV_SQRT_DI, 0.f) * wv;
            score[i][2] += fmaxf(d23.x * INV_SQRT_DI, 0.f) * wv;
            score[i][3] += fmaxf(d23.y * INV_SQRT_DI, 0.f) * wv;
        }
    }
#pragma unroll
    for (int i = 0; i < 4; i++) {
        int s = s0 + si + i;
#pragma unroll
        for (int j = 0; j < 4; j++) {
            int t = t0 + ti + j;
            if (t <= s) iscore[(size_t)s*SQ + t] = score[i][j];
        }
    }
}

// ---------- top-512 (frozen) ----------
__device__ __forceinline__ unsigned forder(float f)
{
    unsigned u = __float_as_uint(f);
    return (u & 0x80000000u) ? ~u : (u | 0x80000000u);
}

__global__ __launch_bounds__(256) void topk_kernel(const float* __restrict__ iscore,
                                                   int* __restrict__ tidx, int* __restrict__ tcnt)
{
    int s = blockIdx.x;
    int n = s + 1;
    int tid = threadIdx.x;
    const float* row = iscore + (size_t)s * SQ;
    int* out = tidx + (size_t)s * TOPK;
    if (n <= TOPK) {
        for (int t = tid; t < n; t += 256) out[t] = t;
        if (tid == 0) tcnt[s] = n;
        return;
    }
    __shared__ int hist[256];
    __shared__ unsigned s_pref;
    __shared__ int s_k;
    __shared__ int sc[256];
    if (tid == 0) { s_pref = 0u; s_k = TOPK; }
    __syncthreads();
    for (int pass = 0; pass < 4; pass++) {
        int sh = 24 - 8 * pass;
        unsigned hmask = (pass == 0) ? 0u : (0xFFFFFFFFu << (sh + 8));
        hist[tid] = 0;
        __syncthreads();
        unsigned pref = s_pref;
        for (int t = tid; t < n; t += 256) {
            unsigned u = forder(row[t]);
            if ((u & hmask) == pref) atomicAdd(&hist[(u >> sh) & 255u], 1);
        }
        __syncthreads();
        if (tid == 0) {
            int k = s_k, c = 0, j = 255;
            for (; j >= 0; j--) {
                if (c + hist[j] >= k) break;
                c += hist[j];
            }
            s_k = k - c;
            s_pref = s_pref | ((unsigned)j << sh);
        }
        __syncthreads();
    }
    unsigned uthr = s_pref;
    int kneed = s_k;
    int chunk = (n + 255) / 256;
    int beg = tid * chunk;
    int end = beg + chunk; if (end > n) end = n;
    int cntg = 0, cnte = 0;
    for (int t = beg; t < end; t++) {
        unsigned u = forder(row[t]);
        if (u > uthr) cntg++;
        else if (u == uthr) cnte++;
    }
    sc[tid] = cntg;
    __syncthreads();
    for (int o = 1; o < 256; o <<= 1) {
        int v = (tid >= o) ? sc[tid - o] : 0;
        __syncthreads();
        sc[tid] += v;
        __syncthreads();
    }
    int offg = sc[tid] - cntg;
    int totalg = sc[255];
    __syncthreads();
    sc[tid] = cnte;
    __syncthreads();
    for (int o = 1; o < 256; o <<= 1) {
        int v = (tid >= o) ? sc[tid - o] : 0;
        __syncthreads();
        sc[tid] += v;
        __syncthreads();
    }
    int offe = sc[tid] - cnte;
    for (int t = beg; t < end; t++) {
        unsigned u = forder(row[t]);
        if (u > uthr) {
            out[offg++] = t;
        } else if (u == uthr) {
            int rank = offe++;
            if (rank < kneed) out[totalg + rank] = t;
        }
    }
    if (tid == 0) tcnt[s] = TOPK;
}

// ---------- absorbed attention v3 (measured 4637.8) ----------
// smem: qap[8*576] ull | ps[512*17] f | psp[512*8] ull | ixs[512] int (cbuf aliases ps)
__global__ __launch_bounds__(256) void attn_v3(
    const float* __restrict__ qabs, const float* __restrict__ q,
    const float* __restrict__ kv, const float* __restrict__ kpe,
    const int* __restrict__ tidx, const int* __restrict__ tcnt,
    float* __restrict__ lat)
{
    int s = blockIdx.x;
    int tid = threadIdx.x, lane = tid & 31, w = tid >> 5;
    int n = tcnt[s];
    extern __shared__ __align__(16) char smraw[];
    ull*   qap = (ull*)smraw;
    float* ps  = (float*)(smraw + 36864);
    ull*   psp = (ull*)(smraw + 36864 + 34816);
    int*   ixs = (int*)(smraw + 36864 + 34816 + 32768);
    ull*   cbuf = (ull*)ps;

    for (int idx = tid; idx < 8*576; idx += 256) {
        int hp = idx / 576, gc = idx - hp*576;
        float f0, f1;
        if (gc < 512) {
            f0 = qabs[((size_t)s*H + 2*hp  )*512 + gc];
            f1 = qabs[((size_t)s*H + 2*hp+1)*512 + gc];
        } else {
            f0 = q[((size_t)s*H + 2*hp  )*DQK + DN + gc - 512];
            f1 = q[((size_t)s*H + 2*hp+1)*DQK + DN + gc - 512];
        }
        qap[idx] = pk2(f0, f1);
    }
    for (int i = tid; i < 512; i += 256) ixs[i] = (i < n) ? tidx[(size_t)s*TOPK + i] : 0;
    __syncthreads();

    int kq = lane >> 3, g8 = lane & 7;
    int nt16 = (n + 15) >> 4;
    for (int T = w; T < nt16; T += 8) {
        int base = T * 16;
        int r0 = ixs[base + kq*4 + 0], r1 = ixs[base + kq*4 + 1];
        int r2 = ixs[base + kq*4 + 2], r3 = ixs[base + kq*4 + 3];
        ull acc[4][8];
#pragma unroll
        for (int i = 0; i < 4; i++)
#pragma unroll
            for (int hp = 0; hp < 8; hp++) acc[i][hp] = 0ULL;
#pragma unroll 4
        for (int st = 0; st < 16; st++) {
            int g = g8 + 8*st;
            float4 k0 = *(const float4*)(kv + (size_t)r0*KRr + g*4);
            float4 k1 = *(const float4*)(kv + (size_t)r1*KRr + g*4);
            float4 k2 = *(const float4*)(kv + (size_t)r2*KRr + g*4);
            float4 k3 = *(const float4*)(kv + (size_t)r3*KRr + g*4);
#pragma unroll
            for (int c = 0; c < 4; c++) {
                float c0 = ((const float*)&k0)[c], c1 = ((const float*)&k1)[c];
                float c2 = ((const float*)&k2)[c], c3 = ((const float*)&k3)[c];
                ull p0 = pk2(c0,c0), p1 = pk2(c1,c1), p2 = pk2(c2,c2), p3 = pk2(c3,c3);
#pragma unroll
                for (int hp = 0; hp < 8; hp++) {
                    ull qa = qap[hp*576 + 4*g + c];
                    fma2(acc[0][hp], p0, qa);
                    fma2(acc[1][hp], p1, qa);
                    fma2(acc[2][hp], p2, qa);
                    fma2(acc[3][hp], p3, qa);
                }
            }
        }
#pragma unroll
        for (int st = 16; st < 18; st++) {
            int g = g8 + 8*st;
            float4 k0 = *(const float4*)(kpe + (size_t)r0*DRR + (g-128)*4);
            float4 k1 = *(const float4*)(kpe + (size_t)r1*DRR + (g-128)*4);
            float4 k2 = *(const float4*)(kpe + (size_t)r2*DRR + (g-128)*4);
            float4 k3 = *(const float4*)(kpe + (size_t)r3*DRR + (g-128)*4);
#pragma unroll
            for (int c = 0; c < 4; c++) {
                float c0 = ((const float*)&k0)[c], c1 = ((const float*)&k1)[c];
                float c2 = ((const float*)&k2)[c], c3 = ((const float*)&k3)[c];
                ull p0 = pk2(c0,c0), p1 = pk2(c1,c1), p2 = pk2(c2,c2), p3 = pk2(c3,c3);
#pragma unroll
                for (int hp = 0; hp < 8; hp++) {
                    ull qa = qap[hp*576 + 4*g + c];
                    fma2(acc[0][hp], p0, qa);
                    fma2(acc[1][hp], p1, qa);
                    fma2(acc[2][hp], p2, qa);
                    fma2(acc[3][hp], p3, qa);
                }
            }
        }
#pragma unroll
        for (int i = 0; i < 4; i++)
#pragma unroll
            for (int hp = 0; hp < 8; hp++) {
                ull v = acc[i][hp];
                v = add2(v, __shfl_xor_sync(0xffffffffu, v, 1));
                v = add2(v, __shfl_xor_sync(0xffffffffu, v, 2));
                v = add2(v, __shfl_xor_sync(0xffffffffu, v, 4));
                acc[i][hp] = v;
            }
        if (g8 == 0) {
#pragma unroll
            for (int i = 0; i < 4; i++) {
                int j = base + kq*4 + i;
#pragma unroll
                for (int hp = 0; hp < 8; hp++) {
                    float2 f = upk2(acc[i][hp]);
                    ps[j*17 + 2*hp]     = f.x * INV_SQRT_DQK;
                    ps[j*17 + 2*hp + 1] = f.y * INV_SQRT_DQK;
                }
            }
        }
    }
    __syncthreads();

    for (int h = 2*w; h < 2*w + 2; h++) {
        float m = -FLT_MAX;
        for (int j = lane; j < n; j += 32) m = fmaxf(m, ps[j*17 + h]);
#pragma unroll
        for (int o = 16; o; o >>= 1) m = fmaxf(m, __shfl_xor_sync(0xffffffffu, m, o));
        float ssum = 0.f;
        for (int j = lane; j < n; j += 32) {
            float e = __expf(ps[j*17 + h] - m);
            ps[j*17 + h] = e; ssum += e;
        }
#pragma unroll
        for (int o = 16; o; o >>= 1) ssum += __shfl_xor_sync(0xffffffffu, ssum, o);
        float inv = 1.f / ssum;
        for (int j = lane; j < n; j += 32) ps[j*17 + h] *= inv;
        for (int j = n + lane; j < 512; j += 32) ps[j*17 + h] = 0.f;
    }
    __syncthreads();

    for (int idx = tid; idx < 4096; idx += 256) {
        int j = idx >> 3, hp = idx & 7;
        psp[idx] = pk2(ps[j*17 + 2*hp], ps[j*17 + 2*hp + 1]);
    }
    __syncthreads();

    int gq = w & 3, par = w >> 2;
    int gran = gq * 32 + lane;
    ull acc2[32];
#pragma unroll
    for (int i = 0; i < 32; i++) acc2[i] = 0ULL;
    for (int j = par; j < n; j += 2) {
        int row = ixs[j];
        float4 v4 = *(const float4*)(kv + (size_t)row * KRr + gran * 4);
        ull c0 = pk2(v4.x,v4.x), c1 = pk2(v4.y,v4.y), c2 = pk2(v4.z,v4.z), c3 = pk2(v4.w,v4.w);
        const ull* pr = psp + j*8;
#pragma unroll
        for (int hp = 0; hp < 8; hp++) {
            ull p = pr[hp];
            fma2(acc2[hp*4+0], c0, p);
            fma2(acc2[hp*4+1], c1, p);
            fma2(acc2[hp*4+2], c2, p);
            fma2(acc2[hp*4+3], c3, p);
        }
    }
    if (par == 1) {
#pragma unroll
        for (int k = 0; k < 32; k++) cbuf[k*128 + gran] = acc2[k];
    }
    __syncthreads();
    if (par == 0) {
#pragma unroll
        for (int k = 0; k < 32; k++) acc2[k] = add2(acc2[k], cbuf[k*128 + gran]);
#pragma unroll
        for (int hp = 0; hp < 8; hp++) {
            float2 u0 = upk2(acc2[hp*4+0]), u1 = upk2(acc2[hp*4+1]);
            float2 u2 = upk2(acc2[hp*4+2]), u3 = upk2(acc2[hp*4+3]);
            *(float4*)(lat + ((size_t)(2*hp  )*SQ + s)*512 + gran*4) = make_float4(u0.x,u1.x,u2.x,u3.x);
            *(float4*)(lat + ((size_t)(2*hp+1)*SQ + s)*512 + gran*4) = make_float4(u0.y,u1.y,u2.y,u3.y);
        }
    }
}

// ---------- host ----------
extern "C" void kernel_launch(void* const* d_in, const int* in_sizes, int n_in,
                              void* d_out, int out_size)
{
    const float *hidden, *cosp, *sinp, *wq_a, *q_norm_w, *wq_b, *wkv_a, *kv_norm_w,
                *wkv_b, *wo, *idx_wq_b, *idx_wk, *idx_kn_w, *idx_kn_b, *idx_wproj;
    if (n_in >= 2 && in_sizes[1] == 3145728) {
        hidden=(const float*)d_in[0];  wq_a=(const float*)d_in[1];
        q_norm_w=(const float*)d_in[2]; wq_b=(const float*)d_in[3];
        wkv_a=(const float*)d_in[4];   kv_norm_w=(const float*)d_in[5];
        wkv_b=(const float*)d_in[6];   wo=(const float*)d_in[7];
        idx_wq_b=(const float*)d_in[8]; idx_wk=(const float*)d_in[9];
        idx_kn_w=(const float*)d_in[10]; idx_kn_b=(const float*)d_in[11];
        idx_wproj=(const float*)d_in[12]; cosp=(const float*)d_in[13];
        sinp=(const float*)d_in[14];
    } else {
        hidden=(const float*)d_in[0];  cosp=(const float*)d_in[1];
        sinp=(const float*)d_in[2];    wq_a=(const float*)d_in[4];
        q_norm_w=(const float*)d_in[5]; wq_b=(const float*)d_in[6];
        wkv_a=(const float*)d_in[7];   kv_norm_w=(const float*)d_in[8];
        wkv_b=(const float*)d_in[9];   wo=(const float*)d_in[10];
        idx_wq_b=(const float*)d_in[11]; idx_wk=(const float*)d_in[12];
        idx_kn_w=(const float*)d_in[13]; idx_kn_b=(const float*)d_in[14];
        idx_wproj=(const float*)d_in[15];
    }
    float *qr, *q, *kvall, *kv, *kpe, *qi, *ki, *wtsb, *iscore, *qabs, *lat, *attnb;
    int *tix, *tcn;
    cudaGetSymbolAddress((void**)&qr, g_qr);
    cudaGetSymbolAddress((void**)&q, g_q);
    cudaGetSymbolAddress((void**)&kvall, g_kvall);
    cudaGetSymbolAddress((void**)&kv, g_kv);
    cudaGetSymbolAddress((void**)&kpe, g_kpe);
    cudaGetSymbolAddress((void**)&qi, g_qi);
    cudaGetSymbolAddress((void**)&ki, g_ki);
    cudaGetSymbolAddress((void**)&wtsb, g_wts);
    cudaGetSymbolAddress((void**)&iscore, g_iscore);
    cudaGetSymbolAddress((void**)&qabs, g_qabs);
    cudaGetSymbolAddress((void**)&lat, g_lat);
    cudaGetSymbolAddress((void**)&attnb, g_attn);
    cudaGetSymbolAddress((void**)&tix, g_tidx);
    cudaGetSymbolAddress((void**)&tcn, g_tcnt);

    const int ISMEM = (128*68 + 64*132 + 64*33) * 4;
    cudaFuncSetAttribute(indexer_kernel, cudaFuncAttributeMaxDynamicSharedMemorySize, ISMEM);
    const int ASMEM = 36864 + 34816 + 32768 + 2048;   // 106496
    cudaFuncSetAttribute(attn_v3, cudaFuncAttributeMaxDynamicSharedMemorySize, ASMEM);

    // ---- frozen indexer path ----
    sgemm_nt<<<dim3(16, 12), 256>>>(hidden, wq_a, qr, SQ, QRr, DM);
    rmsnorm_kernel<<<SQ, 256>>>(qr, q_norm_w, qr, QRr, QRr, QRr, 1e-6f);
    sgemm_nt<<<dim3(16, 32), 256>>>(qr, idx_wq_b, qi, SQ, HIi*DIi, QRr);
    rope_half_qi_kernel<<<(SQ*HIi*32 + 255)/256, 256>>>(qi, cosp, sinp);
    gemm_warpdot<<<(SQ*DIi*32)/256, 256>>>(hidden, idx_wk, ki, SQ, DIi, DM, 1.f);
    layernorm128_kernel<<<SQ, 128>>>(ki, idx_kn_w, idx_kn_b);
    rope_half_ki_kernel<<<(SQ*32 + 255)/256, 256>>>(ki, cosp, sinp);
    gemm_warpdot<<<(SQ*HIi*32)/256, 256>>>(hidden, idx_wproj, wtsb, SQ, HIi, DM, INV_SQRT_HI);

    // ---- value path ----
    gemm_bf16x6<<<dim3((H*DQK)/64, 16), 256>>>(qr, wq_b, q, SQ, H*DQK, QRr, H*DQK, 0, 0, 0);
    rope_inter_q<<<(SQ*H*32 + 255)/256, 256>>>(q, cosp, sinp);
    gemm_bf16x6<<<dim3((KRr+DRR)/64, 16), 256>>>(hidden, wkv_a, kvall, SQ, KRr+DRR, DM, KRr+DRR, 0, 0, 0);
    rmsnorm_kernel<<<SQ, 256>>>(kvall, kv_norm_w, kv, KRr, KRr+DRR, KRr, 1e-6f);
    rope_inter_kpe<<<(SQ*32 + 255)/256, 256>>>(kvall, cosp, sinp, kpe);
    qabsorb_kernel<<<dim3(8, 32, 16), 256>>>(q, wkv_b, qabs);

    // ---- selection ----
    indexer_kernel<<<dim3(32, 32), 256, ISMEM>>>(qi, ki, wtsb, iscore);
    topk_kernel<<<SQ, 256>>>(iscore, tix, tcn);

    // ---- absorbed attention ----
    attn_v3<<<SQ, 256, ASMEM>>>(qabs, q, kv, kpe, tix, tcn, lat);

    // latent -> per-head values
    gemm_bf16x6<<<dim3(2, 16, 16), 256>>>(lat, wkv_b + (size_t)DN*KRr, attnb,
                                          SQ, DV, KRr, H*DV,
                                          (long long)SQ*KRr, (long long)(DN+DV)*KRr, DV);
    // output projection
    gemm_bf16x6<<<dim3(32, 16, 1), 256>>>(attnb, wo, (float*)d_out, SQ, DM, DM, DM, 0, 0, 0);
}